// round 12
// baseline (speedup 1.0000x reference)
#include <cuda_runtime.h>
#include <cuda_bf16.h>
#include <cstdint>

#define BB 16
#define CC 256
#define TT 1024

// Precomputed table (device global: no allocation allowed)
__device__ float g_M[256][9][256];    // [j][t][c]

#define LIF_BLOCKS 512
#define PREP_BASE  512
#define ZF_BASE    1024
#define ZF_BLOCKS  2048
#define TOTAL_BLOCKS (ZF_BASE + ZF_BLOCKS)

__device__ __forceinline__ void pdl_trigger() {
    asm volatile("griddepcontrol.launch_dependents;");
}
__device__ __forceinline__ void pdl_wait() {
    asm volatile("griddepcontrol.wait;");
}

// ---------------------------------------------------------------------------
// Fused producer:
//   blocks [0,512)      : LIF (8 rows each)            -> writes out_x/lat/act
//   blocks [512,1024)   : M prep                        -> writes g_M
//   blocks [1024,3072)  : zero-fill recon [9,1024)      -> triggers PDL early
// LIF/prep blocks count as PDL-triggered when they EXIT (act/M complete).
// ---------------------------------------------------------------------------
__global__ void __launch_bounds__(256)
fused_kernel(const float* __restrict__ x,
             const float* __restrict__ w3, const float* __restrict__ b3,
             const float* __restrict__ w5, const float* __restrict__ b5,
             const float* __restrict__ w9, const float* __restrict__ b9,
             const float* __restrict__ rw, const float* __restrict__ rb,
             const float* __restrict__ ls,
             const float* __restrict__ og, const float* __restrict__ fw,
             float* __restrict__ out_x, float* __restrict__ out_lat,
             float* __restrict__ out_act, float* __restrict__ recon) {
    __shared__ float smem[8 * 33 * 32];                 // 33792 B, reused by roles
    const int bid = blockIdx.x;
    const int tid = threadIdx.x;

    if (bid >= ZF_BASE) {
        // =================== zero-fill role: floats [9,1024) of 2 rows ======
        pdl_trigger();                                   // heads doesn't read this
        const int r0 = (bid - ZF_BASE) * 2;
        const float4 z = make_float4(0.f, 0.f, 0.f, 0.f);
        #pragma unroll
        for (int rr = 0; rr < 2; rr++) {
            float* row = recon + (size_t)(r0 + rr) * TT;
            if (tid < 3) row[9 + tid] = 0.f;             // floats 9,10,11
            float4* zp = (float4*)(row + 12);            // floats [12,1024) = 253 f4
            if (tid < 253) zp[tid] = z;
        }
        return;
    }

    if (bid < LIF_BLOCKS) {
        // =================== LIF role ===================
        const int warp = tid >> 5, lane = tid & 31;
        const int row = bid * 8 + warp;              // b*256+c
        const int c = row & 255;
        const float* xr = x + (size_t)row * TT;
        float* xo = out_x + (size_t)row * TT;
        float* sp = smem + warp * (33 * 32);

        #pragma unroll
        for (int i = 0; i < 8; i++) {
            const int p = i * 128 + lane * 4;
            float4 v = *(const float4*)(xr + p);
            *(float4*)(xo + p) = v;
            const int base = 33 * (p >> 5) + (p & 31);
            sp[base + 0] = v.x; sp[base + 1] = v.y; sp[base + 2] = v.z; sp[base + 3] = v.w;
        }

        // per-warp effective 9-tap kernel
        float ew[9];
        #pragma unroll
        for (int i = 0; i < 9; i++) ew[i] = 0.f;
        float eb = 0.f;
        {
            const int d = lane;
            if (d < 6) {
                float r = rw[c * 18 + d];
                eb = r * b3[c * 6 + d];
                #pragma unroll
                for (int i = 0; i < 3; i++) ew[i + 3] = r * w3[(c * 6 + d) * 3 + i];
            } else if (d < 12) {
                int dd = d - 6;
                float r = rw[c * 18 + d];
                eb = r * b5[c * 6 + dd];
                #pragma unroll
                for (int i = 0; i < 5; i++) ew[i + 2] = r * w5[(c * 6 + dd) * 5 + i];
            } else if (d < 18) {
                int dd = d - 12;
                float r = rw[c * 18 + d];
                eb = r * b9[c * 6 + dd];
                #pragma unroll
                for (int i = 0; i < 9; i++) ew[i] = r * w9[(c * 6 + dd) * 9 + i];
            } else if (d == 31) {
                eb = rb[c];
            }
        }
        #pragma unroll
        for (int off = 16; off; off >>= 1) {
            #pragma unroll
            for (int i = 0; i < 9; i++) ew[i] += __shfl_xor_sync(0xffffffffu, ew[i], off);
            eb += __shfl_xor_sync(0xffffffffu, eb, off);
        }
        __syncwarp();

        const float AL  = (float)0.81873075307798185567;   // exp(-1/5)
        const float OM  = (float)0.18126924692201814433;   // 1 - alpha
        const float A32 = (float)0.00166155727317393354;   // alpha^32

        const int sb = 33 * lane;
        float dloc[32];

        {   // outputs 0..7
            float w[16];
            #pragma unroll
            for (int q = 0; q < 4; q++)  w[q] = (lane > 0) ? sp[sb - 5 + q] : 0.f;
            #pragma unroll
            for (int q = 4; q < 16; q++) w[q] = sp[sb + q - 4];
            #pragma unroll
            for (int k = 0; k < 8; k++) {
                float d = eb;
                #pragma unroll
                for (int i = 0; i < 9; i++) d = fmaf(ew[i], w[k + i], d);
                dloc[k] = d;
            }
        }
        {   // outputs 8..15
            float w[16];
            #pragma unroll
            for (int q = 0; q < 16; q++) w[q] = sp[sb + 4 + q];
            #pragma unroll
            for (int k = 0; k < 8; k++) {
                float d = eb;
                #pragma unroll
                for (int i = 0; i < 9; i++) d = fmaf(ew[i], w[k + i], d);
                dloc[8 + k] = d;
            }
        }
        {   // outputs 16..23
            float w[16];
            #pragma unroll
            for (int q = 0; q < 16; q++) w[q] = sp[sb + 12 + q];
            #pragma unroll
            for (int k = 0; k < 8; k++) {
                float d = eb;
                #pragma unroll
                for (int i = 0; i < 9; i++) d = fmaf(ew[i], w[k + i], d);
                dloc[16 + k] = d;
            }
        }
        {   // outputs 24..31
            float w[16];
            #pragma unroll
            for (int q = 0; q < 12; q++)  w[q] = sp[sb + 20 + q];
            #pragma unroll
            for (int q = 12; q < 16; q++) w[q] = (lane < 31) ? sp[sb + 21 + q] : 0.f;
            #pragma unroll
            for (int k = 0; k < 8; k++) {
                float d = eb;
                #pragma unroll
                for (int i = 0; i < 9; i++) d = fmaf(ew[i], w[k + i], d);
                dloc[24 + k] = d;
            }
        }

        // pass 1: local segment value from V=0
        float U = 0.f, A = A32;
        #pragma unroll
        for (int ss = 0; ss < 32; ss++) U = fmaf(AL, U, OM * dloc[ss]);

        // Kogge-Stone scan over (A,U)
        #pragma unroll
        for (int off = 1; off < 32; off <<= 1) {
            float Au = __shfl_up_sync(0xffffffffu, A, off);
            float Uu = __shfl_up_sync(0xffffffffu, U, off);
            if (lane >= off) { U = fmaf(A, Uu, U); A *= Au; }
        }
        float Vin = __shfl_up_sync(0xffffffffu, U, 1);
        if (lane == 0) Vin = 0.f;

        // pass 2: exact-order replay, first crossing
        float V = Vin;
        int lat = TT;
        const int t0 = lane * 32;
        #pragma unroll
        for (int ss = 0; ss < 32; ss++) {
            V = fmaf(AL, V, OM * dloc[ss]);
            if (lat == TT && V >= 0.01f) lat = t0 + ss;
        }
        #pragma unroll
        for (int off = 16; off; off >>= 1) lat = min(lat, __shfl_xor_sync(0xffffffffu, lat, off));

        if (lane == 0) {
            float latf = (float)lat;
            float sc = fmaxf(ls[0], 0.001f);
            out_lat[row] = latf;
            out_act[row] = expf(-latf / sc);
        }
        return;                                          // exit == PDL trigger
    }

    // =================== M-prep role ===================
    {
        const int m = bid - PREP_BASE;
        const int j = m >> 1;
        const int cbase = (m & 1) * 128;
        const int ci = tid & 127;
        const int c = cbase + ci;
        float* sA = smem;                               // [128][6] used

        if (tid < 128) {
            float f[12];
            {
                const float2* p = reinterpret_cast<const float2*>(fw + ((size_t)j * 256 + c) * 18);
                #pragma unroll
                for (int i = 0; i < 6; i++) { float2 v = p[i]; f[2*i] = v.x; f[2*i+1] = v.y; }
            }
            float s[5];
            #pragma unroll
            for (int t = 0; t < 5; t++) s[t] = 0.f;
            {
                float a[18];
                const float2* p = reinterpret_cast<const float2*>(w3 + c * 18);
                #pragma unroll
                for (int i = 0; i < 9; i++) { float2 v = p[i]; a[2*i] = v.x; a[2*i+1] = v.y; }
                #pragma unroll
                for (int d = 0; d < 6; d++)
                    #pragma unroll
                    for (int t = 0; t < 3; t++) s[t] = fmaf(f[d], a[d*3+t], s[t]);
            }
            {
                float a[30];
                const float2* p = reinterpret_cast<const float2*>(w5 + c * 30);
                #pragma unroll
                for (int i = 0; i < 15; i++) { float2 v = p[i]; a[2*i] = v.x; a[2*i+1] = v.y; }
                #pragma unroll
                for (int d = 0; d < 6; d++)
                    #pragma unroll
                    for (int t = 0; t < 5; t++) s[t] = fmaf(f[6+d], a[d*5+t], s[t]);
            }
            #pragma unroll
            for (int t = 0; t < 5; t++) sA[ci * 6 + t] = s[t];
            __syncthreads();
        } else {
            float f[6];
            {
                const float2* p = reinterpret_cast<const float2*>(fw + ((size_t)j * 256 + c) * 18 + 12);
                #pragma unroll
                for (int i = 0; i < 3; i++) { float2 v = p[i]; f[2*i] = v.x; f[2*i+1] = v.y; }
            }
            const float g = og[(size_t)j * 256 + c];
            float s[9];
            #pragma unroll
            for (int t = 0; t < 9; t++) s[t] = 0.f;
            {
                float a[54];
                const float2* p = reinterpret_cast<const float2*>(w9 + c * 54);
                #pragma unroll
                for (int i = 0; i < 27; i++) { float2 v = p[i]; a[2*i] = v.x; a[2*i+1] = v.y; }
                #pragma unroll
                for (int d = 0; d < 6; d++)
                    #pragma unroll
                    for (int t = 0; t < 9; t++) s[t] = fmaf(f[d], a[d*9+t], s[t]);
            }
            __syncthreads();
            #pragma unroll
            for (int t = 0; t < 5; t++) s[t] += sA[ci * 6 + t];
            #pragma unroll
            for (int t = 0; t < 9; t++) g_M[j][t][c] = g * s[t];
        }
        // exit == PDL trigger (M writes complete)
    }
}

// ---------------------------------------------------------------------------
// heads (PDL secondary): warp per (j,t). 256 blocks x 9 warps; j = bid,
// t = warp. Waits on griddepcontrol, then reads L2-hot M/act.
// ---------------------------------------------------------------------------
__global__ void __launch_bounds__(288)
heads_kernel(const float* __restrict__ act, float* __restrict__ recon) {
    pdl_wait();                                          // producers' M/act visible
    const int j = blockIdx.x;
    const int t = threadIdx.x / 32;
    const int lane = threadIdx.x & 31;

    const float4* mp = reinterpret_cast<const float4*>(&g_M[j][t][lane * 8]);
    const float4 m0 = mp[0], m1 = mp[1];

    float sums[16];
    #pragma unroll
    for (int b = 0; b < 16; b++) {
        const float4* ap = reinterpret_cast<const float4*>(act + b * 256 + lane * 8);
        const float4 a0 = ap[0], a1 = ap[1];
        float s0 = m0.x * a0.x, s1 = m0.y * a0.y, s2 = m0.z * a0.z, s3 = m0.w * a0.w;
        s0 = fmaf(m1.x, a1.x, s0); s1 = fmaf(m1.y, a1.y, s1);
        s2 = fmaf(m1.z, a1.z, s2); s3 = fmaf(m1.w, a1.w, s3);
        sums[b] = (s0 + s1) + (s2 + s3);
    }
    #pragma unroll
    for (int b = 0; b < 16; b++) {
        #pragma unroll
        for (int off = 16; off; off >>= 1)
            sums[b] += __shfl_xor_sync(0xffffffffu, sums[b], off);
    }

    if (lane < 16) {
        float v = sums[0];
        #pragma unroll
        for (int b = 1; b < 16; b++) if (lane == b) v = sums[b];
        recon[((size_t)lane * 256 + j) * TT + t] = v;
    }
}

// ---------------------------------------------------------------------------
extern "C" void kernel_launch(void* const* d_in, const int* in_sizes, int n_in,
                              void* d_out, int out_size) {
    const float* x  = (const float*)d_in[0];
    const float* w3 = (const float*)d_in[1];
    const float* b3 = (const float*)d_in[2];
    const float* w5 = (const float*)d_in[3];
    const float* b5 = (const float*)d_in[4];
    const float* w9 = (const float*)d_in[5];
    const float* b9 = (const float*)d_in[6];
    const float* rw = (const float*)d_in[7];
    const float* rb = (const float*)d_in[8];
    const float* ls = (const float*)d_in[9];
    const float* og = (const float*)d_in[10];
    const float* fw = (const float*)d_in[11];

    float* out      = (float*)d_out;
    float* recon    = out;                         // (B,C,T)  4194304
    float* out_x    = out + 4194304;               // (B,C,T)  4194304
    float* out_lat  = out + 8388608;               // (B,C)       4096
    float* out_act  = out + 8392704;               // (B,C)       4096

    fused_kernel<<<TOTAL_BLOCKS, 256>>>(x, w3, b3, w5, b5, w9, b9, rw, rb, ls,
                                        og, fw, out_x, out_lat, out_act, recon);

    // PDL launch of heads: overlaps with the producer's ZF tail.
    cudaLaunchAttribute attrs[1];
    attrs[0].id = cudaLaunchAttributeProgrammaticStreamSerialization;
    attrs[0].val.programmaticStreamSerializationAllowed = 1;
    cudaLaunchConfig_t cfg = {};
    cfg.gridDim  = dim3(256, 1, 1);
    cfg.blockDim = dim3(288, 1, 1);
    cfg.dynamicSmemBytes = 0;
    cfg.stream = 0;
    cfg.attrs = attrs;
    cfg.numAttrs = 1;
    cudaError_t e = cudaLaunchKernelEx(&cfg, heads_kernel,
                                       (const float*)out_act, (float*)recon);
    if (e != cudaSuccess) {                        // fallback: plain serialized
        heads_kernel<<<256, 288>>>(out_act, recon);
    }
}